// round 4
// baseline (speedup 1.0000x reference)
#include <cuda_runtime.h>

#define TT 1024
#define OO 512
#define DD 256
#define HH 512

__device__ float g_ht[TT * HH];   // z_t @ W1[:D]            [1024,512]
__device__ float g_ho[OO * HH];   // z_o @ W1[D:] + b1       [512,512]
__device__ float g_ct[TT];        // 0.505 * <ht[t], W2>
__device__ float g_co[OO];        // 0.505 * <ho[o], W2> + b2

typedef unsigned long long u64;

__device__ __forceinline__ u64 add2(u64 a, u64 b) {
    u64 d; asm("add.rn.f32x2 %0,%1,%2;" : "=l"(d) : "l"(a), "l"(b)); return d;
}
__device__ __forceinline__ u64 fma2(u64 a, u64 b, u64 c) {
    u64 d; asm("fma.rn.f32x2 %0,%1,%2,%3;" : "=l"(d) : "l"(a), "l"(b), "l"(c)); return d;
}
__device__ __forceinline__ u64 dup2(float v) {
    u64 d; asm("mov.b64 %0,{%1,%1};" : "=l"(d) : "f"(v)); return d;
}

// ---------------------------------------------------------------------------
// Fused GEMM over combined M=1536: rows [0,1024) = z_t@W1[:D],
// rows [1024,1536) = z_o@W1[D:]+b1. BM=64, BN=32, BK=16, 256 threads.
// Micro: 2m (packed pair) x 4n. B staged PRE-DUPLICATED as u64 pairs so the
// inner loop is 1 LDS.64 + 2 LDS.128 + 4 FFMA2 per k (no movs).
// Grid: (512/32=16 n-tiles, 1536/64=24 m-tiles) = 384 CTAs.
// ---------------------------------------------------------------------------
__global__ __launch_bounds__(256) void gemm_kernel(
    const float* __restrict__ z_t, const float* __restrict__ z_o,
    const float* __restrict__ W1,  const float* __restrict__ b1)
{
    __shared__ float As[16][66];    // [k][m] transposed, padded
    __shared__ u64   Bsd[16][32];   // [k][n] pre-duplicated pairs

    const int tid = threadIdx.x;
    const int mt  = blockIdx.y;             // 0..23
    const int n0  = blockIdx.x << 5;        // 0..480
    const bool isHo = (mt >= 16);
    const int m0 = isHo ? ((mt - 16) << 6) : (mt << 6);
    const float* A = isHo ? z_o : z_t;
    const float* B = isHo ? (W1 + (u64)DD * HH) : W1;
    float* C = isHo ? g_ho : g_ht;

    const int arow = tid >> 2;              // 0..63
    const int akv  = (tid & 3) << 2;        // 0,4,8,12
    const int brow = tid >> 4;              // 0..15
    const int bcol = (tid & 15) << 1;       // 0..30

    const int tx = tid & 7;                 // n quad: 4*tx
    const int ty = tid >> 3;                // m pair: 2*ty

    u64 acc[4] = {0ull, 0ull, 0ull, 0ull};

    for (int k0 = 0; k0 < DD; k0 += 16) {
        float4 va = *reinterpret_cast<const float4*>(&A[(u64)(m0 + arow) * DD + k0 + akv]);
        float2 vb = *reinterpret_cast<const float2*>(&B[(u64)(k0 + brow) * HH + n0 + bcol]);
        __syncthreads();
        As[akv + 0][arow] = va.x; As[akv + 1][arow] = va.y;
        As[akv + 2][arow] = va.z; As[akv + 3][arow] = va.w;
        Bsd[brow][bcol]     = dup2(vb.x);
        Bsd[brow][bcol + 1] = dup2(vb.y);
        __syncthreads();

        #pragma unroll
        for (int k = 0; k < 16; k++) {
            u64 ap = *reinterpret_cast<const u64*>(&As[k][ty << 1]);
            ulonglong2 b01 = *reinterpret_cast<const ulonglong2*>(&Bsd[k][tx << 2]);
            ulonglong2 b23 = *reinterpret_cast<const ulonglong2*>(&Bsd[k][(tx << 2) + 2]);
            acc[0] = fma2(ap, b01.x, acc[0]);
            acc[1] = fma2(ap, b01.y, acc[1]);
            acc[2] = fma2(ap, b23.x, acc[2]);
            acc[3] = fma2(ap, b23.y, acc[3]);
        }
    }

    float4 bv = make_float4(0.f, 0.f, 0.f, 0.f);
    if (isHo) bv = *reinterpret_cast<const float4*>(&b1[n0 + (tx << 2)]);

    float2 f0 = *reinterpret_cast<float2*>(&acc[0]);
    float2 f1 = *reinterpret_cast<float2*>(&acc[1]);
    float2 f2 = *reinterpret_cast<float2*>(&acc[2]);
    float2 f3 = *reinterpret_cast<float2*>(&acc[3]);
    int r = m0 + (ty << 1);
    float4 r0 = make_float4(f0.x + bv.x, f1.x + bv.y, f2.x + bv.z, f3.x + bv.w);
    float4 r1 = make_float4(f0.y + bv.x, f1.y + bv.y, f2.y + bv.z, f3.y + bv.w);
    *reinterpret_cast<float4*>(&C[(u64)r * HH + n0 + (tx << 2)])       = r0;
    *reinterpret_cast<float4*>(&C[(u64)(r + 1) * HH + n0 + (tx << 2)]) = r1;
}

// ---------------------------------------------------------------------------
// Per-row linear terms: ct[t] = 0.505*<ht[t],W2>, co[o] = 0.505*<ho[o],W2>+b2
// ---------------------------------------------------------------------------
__global__ __launch_bounds__(256) void reduce_kernel(
    const float* __restrict__ W2, const float* __restrict__ b2)
{
    int warp = (blockIdx.x * blockDim.x + threadIdx.x) >> 5;
    int lane = threadIdx.x & 31;
    const float* row;
    float* dst;
    float extra = 0.f;
    if (warp < TT) { row = g_ht + (u64)warp * HH; dst = g_ct + warp; }
    else { row = g_ho + (u64)(warp - TT) * HH; dst = g_co + (warp - TT); extra = b2[0]; }
    float s = 0.f;
    #pragma unroll
    for (int i = 0; i < 16; i++) s += row[lane + 32 * i] * W2[lane + 32 * i];
    #pragma unroll
    for (int off = 16; off; off >>= 1) s += __shfl_xor_sync(0xffffffffu, s, off);
    if (lane == 0) *dst = 0.505f * s + extra;
}

// ---------------------------------------------------------------------------
// Pairwise kernel: out[t,o] = ct[t]+co[o] + sum_h |ht+ho| * (0.495*W2[h])
// 64x64 tile, 512 threads (16 warps -> 4 warps/SMSP), micro 2t x 4o.
// H chunked by 64 into smem as float4 quads [hq][row]. Packed f32x2 inner.
// ---------------------------------------------------------------------------
__global__ __launch_bounds__(512) void pair_kernel(
    const float* __restrict__ W2, float* __restrict__ out)
{
    __shared__ float4 sA[16][65];      // [hq][t]
    __shared__ float4 sB[16][65];      // [hq][o]
    __shared__ float4 sW[HH / 4];      // 0.495*W2 quads

    const int tid = threadIdx.x;
    const int tx = tid & 15;           // o lane (o = tx + 16j)
    const int ty = (tid >> 4) & 31;    // t lane (t = ty + 32i)
    const int t0 = blockIdx.y << 6;
    const int o0 = blockIdx.x << 6;

    if (tid < HH / 4) {
        float4 w = *reinterpret_cast<const float4*>(&W2[tid << 2]);
        w.x *= 0.495f; w.y *= 0.495f; w.z *= 0.495f; w.w *= 0.495f;
        sW[tid] = w;
    }

    u64 acc[2][4];
    #pragma unroll
    for (int i = 0; i < 2; i++)
        #pragma unroll
        for (int j = 0; j < 4; j++) acc[i][j] = 0ull;

    const int hs  = tid & 15;          // hq for staging
    const int ts2 = tid >> 4;          // 0..31
    const u64 SMASK = 0x7fffffff7fffffffULL;

    for (int c = 0; c < 8; c++) {      // 8 chunks of 64 h
        float4 va0 = *reinterpret_cast<const float4*>(&g_ht[(u64)(t0 + ts2)      * HH + (c << 6) + (hs << 2)]);
        float4 va1 = *reinterpret_cast<const float4*>(&g_ht[(u64)(t0 + ts2 + 32) * HH + (c << 6) + (hs << 2)]);
        float4 vb0 = *reinterpret_cast<const float4*>(&g_ho[(u64)(o0 + ts2)      * HH + (c << 6) + (hs << 2)]);
        float4 vb1 = *reinterpret_cast<const float4*>(&g_ho[(u64)(o0 + ts2 + 32) * HH + (c << 6) + (hs << 2)]);
        __syncthreads();
        sA[hs][ts2] = va0; sA[hs][ts2 + 32] = va1;
        sB[hs][ts2] = vb0; sB[hs][ts2 + 32] = vb1;
        __syncthreads();

        #pragma unroll
        for (int hq = 0; hq < 16; hq++) {
            ulonglong2 w = *reinterpret_cast<const ulonglong2*>(&sW[(c << 4) + hq]);
            ulonglong2 a[2], b[4];
            #pragma unroll
            for (int i = 0; i < 2; i++)
                a[i] = *reinterpret_cast<const ulonglong2*>(&sA[hq][ty + (i << 5)]);
            #pragma unroll
            for (int j = 0; j < 4; j++)
                b[j] = *reinterpret_cast<const ulonglong2*>(&sB[hq][tx + (j << 4)]);
            #pragma unroll
            for (int i = 0; i < 2; i++)
                #pragma unroll
                for (int j = 0; j < 4; j++) {
                    u64 x = add2(a[i].x, b[j].x) & SMASK;
                    acc[i][j] = fma2(x, w.x, acc[i][j]);
                    u64 y = add2(a[i].y, b[j].y) & SMASK;
                    acc[i][j] = fma2(y, w.y, acc[i][j]);
                }
        }
    }

    float ctv[2], cov[4];
    #pragma unroll
    for (int i = 0; i < 2; i++) ctv[i] = g_ct[t0 + ty + (i << 5)];
    #pragma unroll
    for (int j = 0; j < 4; j++) cov[j] = g_co[o0 + tx + (j << 4)];
    #pragma unroll
    for (int i = 0; i < 2; i++)
        #pragma unroll
        for (int j = 0; j < 4; j++) {
            float2 p = *reinterpret_cast<float2*>(&acc[i][j]);
            out[(u64)(t0 + ty + (i << 5)) * OO + o0 + tx + (j << 4)]
                = ctv[i] + cov[j] + p.x + p.y;
        }
}

extern "C" void kernel_launch(void* const* d_in, const int* in_sizes, int n_in,
                              void* d_out, int out_size)
{
    const float* z_t = (const float*)d_in[0];   // [1024,256]
    const float* z_o = (const float*)d_in[1];   // [512,256]
    const float* W1  = (const float*)d_in[2];   // [512,512]
    const float* b1  = (const float*)d_in[3];   // [512]
    const float* W2  = (const float*)d_in[4];   // [512,1]
    const float* b2  = (const float*)d_in[5];   // [1]
    float* out = (float*)d_out;                 // [1024,512]

    // Both GEMM halves in one launch: grid (16 n-tiles, 24 m-tiles)
    gemm_kernel<<<dim3(16, 24), 256>>>(z_t, z_o, W1, b1);
    // linear terms
    reduce_kernel<<<192, 256>>>(W2, b2);
    // pairwise |.| kernel (128 CTAs x 512 threads)
    pair_kernel<<<dim3(OO / 64, TT / 64), 512>>>(W2, out);
}

// round 7
// speedup vs baseline: 1.5734x; 1.5734x over previous
#include <cuda_runtime.h>

#define TT 1024
#define OO 512
#define DD 256
#define HH 512

__device__ float g_ht[TT * HH];   // z_t @ W1[:D]            [1024,512]
__device__ float g_ho[OO * HH];   // z_o @ W1[D:] + b1       [512,512]
__device__ float g_ct[TT];        // 0.505 * <ht[t], W2>
__device__ float g_co[OO];        // 0.505 * <ho[o], W2> + b2

typedef unsigned long long u64;

__device__ __forceinline__ u64 add2(u64 a, u64 b) {
    u64 d; asm("add.rn.f32x2 %0,%1,%2;" : "=l"(d) : "l"(a), "l"(b)); return d;
}
__device__ __forceinline__ u64 fma2(u64 a, u64 b, u64 c) {
    u64 d; asm("fma.rn.f32x2 %0,%1,%2,%3;" : "=l"(d) : "l"(a), "l"(b), "l"(c)); return d;
}
__device__ __forceinline__ u64 dup2(float v) {
    u64 d; asm("mov.b64 %0,{%1,%1};" : "=l"(d) : "f"(v)); return d;
}

// ---------------------------------------------------------------------------
// Fused GEMM over combined M=1536: rows [0,1024)=z_t@W1[:D],
// [1024,1536)=z_o@W1[D:]+b1. BM=64, BN=32, BK=16, 128 threads.
// Micro 8m(4 packed pairs) x 2n: per k = 2 LDS.128(a) + 1 LDS.128(b, predup)
// + 8 FFMA2. Grid (16 n, 24 m) = 384 CTAs. Next k0-block prefetched to regs.
// As padded to 68 floats/row (272 B = 17*16) so 16B LDS stays aligned.
// ---------------------------------------------------------------------------
__global__ __launch_bounds__(128) void gemm_kernel(
    const float* __restrict__ z_t, const float* __restrict__ z_o,
    const float* __restrict__ W1,  const float* __restrict__ b1)
{
    __shared__ float As[16][68];    // [k][m]; 68*4=272B row -> 16B aligned
    __shared__ u64   Bsd[16][34];   // [k][n] pre-duplicated pairs; 272B row

    const int tid = threadIdx.x;
    const int mt  = blockIdx.y;             // 0..23
    const int n0  = blockIdx.x << 5;        // 0..480
    const bool isHo = (mt >= 16);
    const int m0 = isHo ? ((mt - 16) << 6) : (mt << 6);
    const float* A = isHo ? z_o : z_t;
    const float* B = isHo ? (W1 + (u64)DD * HH) : W1;
    float* C = isHo ? g_ho : g_ht;

    // staging indices
    const int arow = tid & 63;              // 0..63
    const int ah   = (tid >> 6) << 3;       // 0 or 8 (k sub-block)
    const int brow = tid >> 3;              // 0..15
    const int bc4  = (tid & 7) << 2;        // 0,4,..,28

    // compute indices
    const int tx = tid & 15;                // n pair: 2*tx
    const int ty = tid >> 4;                // m oct: 8*ty

    u64 acc[4][2];
    #pragma unroll
    for (int p = 0; p < 4; p++) { acc[p][0] = 0ull; acc[p][1] = 0ull; }

    const float* aptr = &A[(u64)(m0 + arow) * DD + ah];
    const float* bptr = &B[(u64)brow * HH + n0 + bc4];

    float4 va0 = *reinterpret_cast<const float4*>(aptr);
    float4 va1 = *reinterpret_cast<const float4*>(aptr + 4);
    float4 vb  = *reinterpret_cast<const float4*>(bptr);

    #pragma unroll 1
    for (int kb = 0; kb < 16; kb++) {
        __syncthreads();
        As[ah + 0][arow] = va0.x; As[ah + 1][arow] = va0.y;
        As[ah + 2][arow] = va0.z; As[ah + 3][arow] = va0.w;
        As[ah + 4][arow] = va1.x; As[ah + 5][arow] = va1.y;
        As[ah + 6][arow] = va1.z; As[ah + 7][arow] = va1.w;
        Bsd[brow][bc4 + 0] = dup2(vb.x);
        Bsd[brow][bc4 + 1] = dup2(vb.y);
        Bsd[brow][bc4 + 2] = dup2(vb.z);
        Bsd[brow][bc4 + 3] = dup2(vb.w);
        __syncthreads();

        if (kb < 15) {   // prefetch next k0 block while computing this one
            const float* ap = aptr + (kb + 1) * 16;
            va0 = *reinterpret_cast<const float4*>(ap);
            va1 = *reinterpret_cast<const float4*>(ap + 4);
            vb  = *reinterpret_cast<const float4*>(bptr + (u64)(kb + 1) * 16 * HH);
        }

        #pragma unroll
        for (int k = 0; k < 16; k++) {
            ulonglong2 a01 = *reinterpret_cast<const ulonglong2*>(&As[k][ty << 3]);
            ulonglong2 a23 = *reinterpret_cast<const ulonglong2*>(&As[k][(ty << 3) + 4]);
            ulonglong2 b01 = *reinterpret_cast<const ulonglong2*>(&Bsd[k][tx << 1]);
            acc[0][0] = fma2(a01.x, b01.x, acc[0][0]);
            acc[0][1] = fma2(a01.x, b01.y, acc[0][1]);
            acc[1][0] = fma2(a01.y, b01.x, acc[1][0]);
            acc[1][1] = fma2(a01.y, b01.y, acc[1][1]);
            acc[2][0] = fma2(a23.x, b01.x, acc[2][0]);
            acc[2][1] = fma2(a23.x, b01.y, acc[2][1]);
            acc[3][0] = fma2(a23.y, b01.x, acc[3][0]);
            acc[3][1] = fma2(a23.y, b01.y, acc[3][1]);
        }
    }

    float2 bv = make_float2(0.f, 0.f);
    if (isHo) bv = *reinterpret_cast<const float2*>(&b1[n0 + (tx << 1)]);

    #pragma unroll
    for (int p = 0; p < 4; p++) {
        float2 f0 = *reinterpret_cast<float2*>(&acc[p][0]);   // {m, m+1} for n
        float2 f1 = *reinterpret_cast<float2*>(&acc[p][1]);   // {m, m+1} for n+1
        int r = m0 + (ty << 3) + (p << 1);
        float2 r0 = make_float2(f0.x + bv.x, f1.x + bv.y);
        float2 r1 = make_float2(f0.y + bv.x, f1.y + bv.y);
        *reinterpret_cast<float2*>(&C[(u64)r * HH + n0 + (tx << 1)])       = r0;
        *reinterpret_cast<float2*>(&C[(u64)(r + 1) * HH + n0 + (tx << 1)]) = r1;
    }
}

// ---------------------------------------------------------------------------
// Per-row linear terms: ct[t] = 0.505*<ht[t],W2>, co[o] = 0.505*<ho[o],W2>+b2
// ---------------------------------------------------------------------------
__global__ __launch_bounds__(256) void reduce_kernel(
    const float* __restrict__ W2, const float* __restrict__ b2)
{
    int warp = (blockIdx.x * blockDim.x + threadIdx.x) >> 5;
    int lane = threadIdx.x & 31;
    const float* row;
    float* dst;
    float extra = 0.f;
    if (warp < TT) { row = g_ht + (u64)warp * HH; dst = g_ct + warp; }
    else { row = g_ho + (u64)(warp - TT) * HH; dst = g_co + (warp - TT); extra = b2[0]; }
    float s = 0.f;
    #pragma unroll
    for (int i = 0; i < 4; i++) {
        float4 v = *reinterpret_cast<const float4*>(&row[(lane + 32 * i) << 2]);
        float4 w = *reinterpret_cast<const float4*>(&W2[(lane + 32 * i) << 2]);
        s += v.x * w.x + v.y * w.y + v.z * w.z + v.w * w.w;
    }
    #pragma unroll
    for (int off = 16; off; off >>= 1) s += __shfl_xor_sync(0xffffffffu, s, off);
    if (lane == 0) *dst = 0.505f * s + extra;
}

// ---------------------------------------------------------------------------
// Pairwise kernel: out[t,o] = ct[t]+co[o] + sum_h |ht+ho| * (0.495*W2[h])
// 64x64 tile, 512 threads (4 warps/SMSP), micro 2t x 4o, packed f32x2 inner.
// Next chunk's global loads prefetched to regs before the 16-hq compute.
// ---------------------------------------------------------------------------
__global__ __launch_bounds__(512) void pair_kernel(
    const float* __restrict__ W2, float* __restrict__ out)
{
    __shared__ float4 sA[16][65];      // [hq][t]
    __shared__ float4 sB[16][65];      // [hq][o]
    __shared__ float4 sW[HH / 4];      // 0.495*W2 quads

    const int tid = threadIdx.x;
    const int tx = tid & 15;           // o lane (o = tx + 16j)
    const int ty = (tid >> 4) & 31;    // t lane (t = ty + 32i)
    const int t0 = blockIdx.y << 6;
    const int o0 = blockIdx.x << 6;

    if (tid < HH / 4) {
        float4 w = *reinterpret_cast<const float4*>(&W2[tid << 2]);
        w.x *= 0.495f; w.y *= 0.495f; w.z *= 0.495f; w.w *= 0.495f;
        sW[tid] = w;
    }

    u64 acc[2][4];
    #pragma unroll
    for (int i = 0; i < 2; i++)
        #pragma unroll
        for (int j = 0; j < 4; j++) acc[i][j] = 0ull;

    const int hs  = tid & 15;          // hq for staging
    const int ts2 = tid >> 4;          // 0..31
    const u64 SMASK = 0x7fffffff7fffffffULL;

    const float* pa0 = &g_ht[(u64)(t0 + ts2)      * HH + (hs << 2)];
    const float* pa1 = &g_ht[(u64)(t0 + ts2 + 32) * HH + (hs << 2)];
    const float* pb0 = &g_ho[(u64)(o0 + ts2)      * HH + (hs << 2)];
    const float* pb1 = &g_ho[(u64)(o0 + ts2 + 32) * HH + (hs << 2)];

    float4 va0 = *reinterpret_cast<const float4*>(pa0);
    float4 va1 = *reinterpret_cast<const float4*>(pa1);
    float4 vb0 = *reinterpret_cast<const float4*>(pb0);
    float4 vb1 = *reinterpret_cast<const float4*>(pb1);

    #pragma unroll 1
    for (int c = 0; c < 8; c++) {      // 8 chunks of 64 h
        __syncthreads();
        sA[hs][ts2] = va0; sA[hs][ts2 + 32] = va1;
        sB[hs][ts2] = vb0; sB[hs][ts2 + 32] = vb1;
        __syncthreads();

        if (c < 7) {                   // prefetch next chunk under compute
            int off = (c + 1) << 6;
            va0 = *reinterpret_cast<const float4*>(pa0 + off);
            va1 = *reinterpret_cast<const float4*>(pa1 + off);
            vb0 = *reinterpret_cast<const float4*>(pb0 + off);
            vb1 = *reinterpret_cast<const float4*>(pb1 + off);
        }

        #pragma unroll
        for (int hq = 0; hq < 16; hq++) {
            ulonglong2 w = *reinterpret_cast<const ulonglong2*>(&sW[(c << 4) + hq]);
            ulonglong2 a[2], b[4];
            #pragma unroll
            for (int i = 0; i < 2; i++)
                a[i] = *reinterpret_cast<const ulonglong2*>(&sA[hq][ty + (i << 5)]);
            #pragma unroll
            for (int j = 0; j < 4; j++)
                b[j] = *reinterpret_cast<const ulonglong2*>(&sB[hq][tx + (j << 4)]);
            #pragma unroll
            for (int i = 0; i < 2; i++)
                #pragma unroll
                for (int j = 0; j < 4; j++) {
                    u64 x = add2(a[i].x, b[j].x) & SMASK;
                    acc[i][j] = fma2(x, w.x, acc[i][j]);
                    u64 y = add2(a[i].y, b[j].y) & SMASK;
                    acc[i][j] = fma2(y, w.y, acc[i][j]);
                }
        }
    }

    float ctv[2], cov[4];
    #pragma unroll
    for (int i = 0; i < 2; i++) ctv[i] = g_ct[t0 + ty + (i << 5)];
    #pragma unroll
    for (int j = 0; j < 4; j++) cov[j] = g_co[o0 + tx + (j << 4)];
    #pragma unroll
    for (int i = 0; i < 2; i++)
        #pragma unroll
        for (int j = 0; j < 4; j++) {
            float2 p = *reinterpret_cast<float2*>(&acc[i][j]);
            out[(u64)(t0 + ty + (i << 5)) * OO + o0 + tx + (j << 4)]
                = ctv[i] + cov[j] + p.x + p.y;
        }
}

extern "C" void kernel_launch(void* const* d_in, const int* in_sizes, int n_in,
                              void* d_out, int out_size)
{
    const float* z_t = (const float*)d_in[0];   // [1024,256]
    const float* z_o = (const float*)d_in[1];   // [512,256]
    const float* W1  = (const float*)d_in[2];   // [512,512]
    const float* b1  = (const float*)d_in[3];   // [512]
    const float* W2  = (const float*)d_in[4];   // [512,1]
    const float* b2  = (const float*)d_in[5];   // [1]
    float* out = (float*)d_out;                 // [1024,512]

    gemm_kernel<<<dim3(16, 24), 128>>>(z_t, z_o, W1, b1);
    reduce_kernel<<<192, 256>>>(W2, b2);
    pair_kernel<<<dim3(OO / 64, TT / 64), 512>>>(W2, out);
}

// round 8
// speedup vs baseline: 1.6162x; 1.0273x over previous
#include <cuda_runtime.h>

#define TT 1024
#define OO 512
#define DD 256
#define HH 512

__device__ float g_ht[TT * HH];   // z_t @ W1[:D]            [1024,512]
__device__ float g_ho[OO * HH];   // z_o @ W1[D:] + b1       [512,512]
__device__ float g_ct[TT];        // 0.505 * <ht[t], W2>
__device__ float g_co[OO];        // 0.505 * <ho[o], W2> + b2

typedef unsigned long long u64;

__device__ __forceinline__ u64 add2(u64 a, u64 b) {
    u64 d; asm("add.rn.f32x2 %0,%1,%2;" : "=l"(d) : "l"(a), "l"(b)); return d;
}
__device__ __forceinline__ u64 fma2(u64 a, u64 b, u64 c) {
    u64 d; asm("fma.rn.f32x2 %0,%1,%2,%3;" : "=l"(d) : "l"(a), "l"(b), "l"(c)); return d;
}
__device__ __forceinline__ u64 dup2(float v) {
    u64 d; asm("mov.b64 %0,{%1,%1};" : "=l"(d) : "f"(v)); return d;
}

// ---------------------------------------------------------------------------
// Fused GEMM over combined M=1536: rows [0,1024)=z_t@W1[:D],
// [1024,1536)=z_o@W1[D:]+b1. BM=64, BN=32, BK=32, 128 threads,
// DOUBLE-BUFFERED smem: 1 syncthreads per 32-k block (8 total).
// Micro 8m(4 packed pairs) x 2n: per k = 2 LDS.128(a) + 1 LDS.128(b, predup)
// + 8 FFMA2. Grid (16 n, 24 m) = 384 CTAs.
// ---------------------------------------------------------------------------
__global__ __launch_bounds__(128) void gemm_kernel(
    const float* __restrict__ z_t, const float* __restrict__ z_o,
    const float* __restrict__ W1,  const float* __restrict__ b1)
{
    __shared__ float As[2][32][68];   // [buf][k][m]; 272B row -> 16B aligned
    __shared__ u64   Bsd[2][32][34];  // [buf][k][n] pre-dup pairs; 272B row

    const int tid = threadIdx.x;
    const int mt  = blockIdx.y;             // 0..23
    const int n0  = blockIdx.x << 5;        // 0..480
    const bool isHo = (mt >= 16);
    const int m0 = isHo ? ((mt - 16) << 6) : (mt << 6);
    const float* A = isHo ? z_o : z_t;
    const float* B = isHo ? (W1 + (u64)DD * HH) : W1;
    float* C = isHo ? g_ho : g_ht;

    // A staging: row = tid&63, k-half = (tid>>6)*16, 4 x float4 (16 k)
    const int arow = tid & 63;
    const int ah   = (tid >> 6) << 4;       // 0 or 16
    // B staging: brow = tid>>2 (0..31), bc = (tid&3)*8, 2 x float4 (8 n)
    const int brow = tid >> 2;
    const int bc   = (tid & 3) << 3;

    // compute indices
    const int tx = tid & 15;                // n pair: 2*tx
    const int ty = tid >> 4;                // m oct: 8*ty

    u64 acc[4][2];
    #pragma unroll
    for (int p = 0; p < 4; p++) { acc[p][0] = 0ull; acc[p][1] = 0ull; }

    const float* aptr = &A[(u64)(m0 + arow) * DD + ah];
    const float* bptr = &B[(u64)brow * HH + n0 + bc];

    float4 va[4], vb[2];

    // ---- prologue: stage 0 ----
    #pragma unroll
    for (int q = 0; q < 4; q++)
        va[q] = *reinterpret_cast<const float4*>(aptr + (q << 2));
    vb[0] = *reinterpret_cast<const float4*>(bptr);
    vb[1] = *reinterpret_cast<const float4*>(bptr + 4);

    #pragma unroll
    for (int q = 0; q < 4; q++) {
        As[0][ah + (q << 2) + 0][arow] = va[q].x;
        As[0][ah + (q << 2) + 1][arow] = va[q].y;
        As[0][ah + (q << 2) + 2][arow] = va[q].z;
        As[0][ah + (q << 2) + 3][arow] = va[q].w;
    }
    Bsd[0][brow][bc + 0] = dup2(vb[0].x); Bsd[0][brow][bc + 1] = dup2(vb[0].y);
    Bsd[0][brow][bc + 2] = dup2(vb[0].z); Bsd[0][brow][bc + 3] = dup2(vb[0].w);
    Bsd[0][brow][bc + 4] = dup2(vb[1].x); Bsd[0][brow][bc + 5] = dup2(vb[1].y);
    Bsd[0][brow][bc + 6] = dup2(vb[1].z); Bsd[0][brow][bc + 7] = dup2(vb[1].w);
    __syncthreads();

    #pragma unroll 1
    for (int kb = 0; kb < 8; kb++) {
        const int cur = kb & 1, nxt = cur ^ 1;

        if (kb < 7) {   // issue next stage's global loads (hidden under compute)
            const float* ap = aptr + ((kb + 1) << 5);
            #pragma unroll
            for (int q = 0; q < 4; q++)
                va[q] = *reinterpret_cast<const float4*>(ap + (q << 2));
            const float* bp = bptr + (u64)((kb + 1) << 5) * HH;
            vb[0] = *reinterpret_cast<const float4*>(bp);
            vb[1] = *reinterpret_cast<const float4*>(bp + 4);
        }

        #pragma unroll
        for (int k = 0; k < 32; k++) {
            ulonglong2 a01 = *reinterpret_cast<const ulonglong2*>(&As[cur][k][ty << 3]);
            ulonglong2 a23 = *reinterpret_cast<const ulonglong2*>(&As[cur][k][(ty << 3) + 4]);
            ulonglong2 b01 = *reinterpret_cast<const ulonglong2*>(&Bsd[cur][k][tx << 1]);
            acc[0][0] = fma2(a01.x, b01.x, acc[0][0]);
            acc[0][1] = fma2(a01.x, b01.y, acc[0][1]);
            acc[1][0] = fma2(a01.y, b01.x, acc[1][0]);
            acc[1][1] = fma2(a01.y, b01.y, acc[1][1]);
            acc[2][0] = fma2(a23.x, b01.x, acc[2][0]);
            acc[2][1] = fma2(a23.x, b01.y, acc[2][1]);
            acc[3][0] = fma2(a23.y, b01.x, acc[3][0]);
            acc[3][1] = fma2(a23.y, b01.y, acc[3][1]);
        }

        if (kb < 7) {   // store into the other buffer (safe: all warps passed
                        // the sync at end of kb-1, done reading buffer nxt)
            #pragma unroll
            for (int q = 0; q < 4; q++) {
                As[nxt][ah + (q << 2) + 0][arow] = va[q].x;
                As[nxt][ah + (q << 2) + 1][arow] = va[q].y;
                As[nxt][ah + (q << 2) + 2][arow] = va[q].z;
                As[nxt][ah + (q << 2) + 3][arow] = va[q].w;
            }
            Bsd[nxt][brow][bc + 0] = dup2(vb[0].x); Bsd[nxt][brow][bc + 1] = dup2(vb[0].y);
            Bsd[nxt][brow][bc + 2] = dup2(vb[0].z); Bsd[nxt][brow][bc + 3] = dup2(vb[0].w);
            Bsd[nxt][brow][bc + 4] = dup2(vb[1].x); Bsd[nxt][brow][bc + 5] = dup2(vb[1].y);
            Bsd[nxt][brow][bc + 6] = dup2(vb[1].z); Bsd[nxt][brow][bc + 7] = dup2(vb[1].w);
            __syncthreads();
        }
    }

    float2 bv = make_float2(0.f, 0.f);
    if (isHo) bv = *reinterpret_cast<const float2*>(&b1[n0 + (tx << 1)]);

    #pragma unroll
    for (int p = 0; p < 4; p++) {
        float2 f0 = *reinterpret_cast<float2*>(&acc[p][0]);   // {m, m+1} for n
        float2 f1 = *reinterpret_cast<float2*>(&acc[p][1]);   // {m, m+1} for n+1
        int r = m0 + (ty << 3) + (p << 1);
        float2 r0 = make_float2(f0.x + bv.x, f1.x + bv.y);
        float2 r1 = make_float2(f0.y + bv.x, f1.y + bv.y);
        *reinterpret_cast<float2*>(&C[(u64)r * HH + n0 + (tx << 1)])       = r0;
        *reinterpret_cast<float2*>(&C[(u64)(r + 1) * HH + n0 + (tx << 1)]) = r1;
    }
}

// ---------------------------------------------------------------------------
// Per-row linear terms: ct[t] = 0.505*<ht[t],W2>, co[o] = 0.505*<ho[o],W2>+b2
// ---------------------------------------------------------------------------
__global__ __launch_bounds__(256) void reduce_kernel(
    const float* __restrict__ W2, const float* __restrict__ b2)
{
    int warp = (blockIdx.x * blockDim.x + threadIdx.x) >> 5;
    int lane = threadIdx.x & 31;
    const float* row;
    float* dst;
    float extra = 0.f;
    if (warp < TT) { row = g_ht + (u64)warp * HH; dst = g_ct + warp; }
    else { row = g_ho + (u64)(warp - TT) * HH; dst = g_co + (warp - TT); extra = b2[0]; }
    float s = 0.f;
    #pragma unroll
    for (int i = 0; i < 4; i++) {
        float4 v = *reinterpret_cast<const float4*>(&row[(lane + 32 * i) << 2]);
        float4 w = *reinterpret_cast<const float4*>(&W2[(lane + 32 * i) << 2]);
        s += v.x * w.x + v.y * w.y + v.z * w.z + v.w * w.w;
    }
    #pragma unroll
    for (int off = 16; off; off >>= 1) s += __shfl_xor_sync(0xffffffffu, s, off);
    if (lane == 0) *dst = 0.505f * s + extra;
}

// ---------------------------------------------------------------------------
// Pairwise kernel: out[t,o] = ct[t]+co[o] + sum_h |ht+ho| * (0.495*W2[h])
// 64x64 tile, 512 threads (4 warps/SMSP), micro 2t x 4o, packed f32x2 inner.
// ---------------------------------------------------------------------------
__global__ __launch_bounds__(512) void pair_kernel(
    const float* __restrict__ W2, float* __restrict__ out)
{
    __shared__ float4 sA[16][65];      // [hq][t]
    __shared__ float4 sB[16][65];      // [hq][o]
    __shared__ float4 sW[HH / 4];      // 0.495*W2 quads

    const int tid = threadIdx.x;
    const int tx = tid & 15;           // o lane (o = tx + 16j)
    const int ty = (tid >> 4) & 31;    // t lane (t = ty + 32i)
    const int t0 = blockIdx.y << 6;
    const int o0 = blockIdx.x << 6;

    if (tid < HH / 4) {
        float4 w = *reinterpret_cast<const float4*>(&W2[tid << 2]);
        w.x *= 0.495f; w.y *= 0.495f; w.z *= 0.495f; w.w *= 0.495f;
        sW[tid] = w;
    }

    u64 acc[2][4];
    #pragma unroll
    for (int i = 0; i < 2; i++)
        #pragma unroll
        for (int j = 0; j < 4; j++) acc[i][j] = 0ull;

    const int hs  = tid & 15;          // hq for staging
    const int ts2 = tid >> 4;          // 0..31
    const u64 SMASK = 0x7fffffff7fffffffULL;

    const float* pa0 = &g_ht[(u64)(t0 + ts2)      * HH + (hs << 2)];
    const float* pa1 = &g_ht[(u64)(t0 + ts2 + 32) * HH + (hs << 2)];
    const float* pb0 = &g_ho[(u64)(o0 + ts2)      * HH + (hs << 2)];
    const float* pb1 = &g_ho[(u64)(o0 + ts2 + 32) * HH + (hs << 2)];

    float4 va0 = *reinterpret_cast<const float4*>(pa0);
    float4 va1 = *reinterpret_cast<const float4*>(pa1);
    float4 vb0 = *reinterpret_cast<const float4*>(pb0);
    float4 vb1 = *reinterpret_cast<const float4*>(pb1);

    #pragma unroll 1
    for (int c = 0; c < 8; c++) {      // 8 chunks of 64 h
        __syncthreads();
        sA[hs][ts2] = va0; sA[hs][ts2 + 32] = va1;
        sB[hs][ts2] = vb0; sB[hs][ts2 + 32] = vb1;
        __syncthreads();

        if (c < 7) {                   // prefetch next chunk under compute
            int off = (c + 1) << 6;
            va0 = *reinterpret_cast<const float4*>(pa0 + off);
            va1 = *reinterpret_cast<const float4*>(pa1 + off);
            vb0 = *reinterpret_cast<const float4*>(pb0 + off);
            vb1 = *reinterpret_cast<const float4*>(pb1 + off);
        }

        #pragma unroll
        for (int hq = 0; hq < 16; hq++) {
            ulonglong2 w = *reinterpret_cast<const ulonglong2*>(&sW[(c << 4) + hq]);
            ulonglong2 a[2], b[4];
            #pragma unroll
            for (int i = 0; i < 2; i++)
                a[i] = *reinterpret_cast<const ulonglong2*>(&sA[hq][ty + (i << 5)]);
            #pragma unroll
            for (int j = 0; j < 4; j++)
                b[j] = *reinterpret_cast<const ulonglong2*>(&sB[hq][tx + (j << 4)]);
            #pragma unroll
            for (int i = 0; i < 2; i++)
                #pragma unroll
                for (int j = 0; j < 4; j++) {
                    u64 x = add2(a[i].x, b[j].x) & SMASK;
                    acc[i][j] = fma2(x, w.x, acc[i][j]);
                    u64 y = add2(a[i].y, b[j].y) & SMASK;
                    acc[i][j] = fma2(y, w.y, acc[i][j]);
                }
        }
    }

    float ctv[2], cov[4];
    #pragma unroll
    for (int i = 0; i < 2; i++) ctv[i] = g_ct[t0 + ty + (i << 5)];
    #pragma unroll
    for (int j = 0; j < 4; j++) cov[j] = g_co[o0 + tx + (j << 4)];
    #pragma unroll
    for (int i = 0; i < 2; i++)
        #pragma unroll
        for (int j = 0; j < 4; j++) {
            float2 p = *reinterpret_cast<float2*>(&acc[i][j]);
            out[(u64)(t0 + ty + (i << 5)) * OO + o0 + tx + (j << 4)]
                = ctv[i] + cov[j] + p.x + p.y;
        }
}

extern "C" void kernel_launch(void* const* d_in, const int* in_sizes, int n_in,
                              void* d_out, int out_size)
{
    const float* z_t = (const float*)d_in[0];   // [1024,256]
    const float* z_o = (const float*)d_in[1];   // [512,256]
    const float* W1  = (const float*)d_in[2];   // [512,512]
    const float* b1  = (const float*)d_in[3];   // [512]
    const float* W2  = (const float*)d_in[4];   // [512,1]
    const float* b2  = (const float*)d_in[5];   // [1]
    float* out = (float*)d_out;                 // [1024,512]

    gemm_kernel<<<dim3(16, 24), 128>>>(z_t, z_o, W1, b1);
    reduce_kernel<<<192, 256>>>(W2, b2);
    pair_kernel<<<dim3(OO / 64, TT / 64), 512>>>(W2, out);
}

// round 9
// speedup vs baseline: 1.6735x; 1.0354x over previous
#include <cuda_runtime.h>

#define TT 1024
#define OO 512
#define DD 256
#define HH 512

__device__ float g_ht[TT * HH];   // z_t @ W1[:D]            [1024,512]
__device__ float g_ho[OO * HH];   // z_o @ W1[D:] + b1       [512,512]
__device__ float g_ct[TT];        // 0.505 * <ht[t], W2>
__device__ float g_co[OO];        // 0.505 * <ho[o], W2> + b2

typedef unsigned long long u64;

__device__ __forceinline__ u64 add2(u64 a, u64 b) {
    u64 d; asm("add.rn.f32x2 %0,%1,%2;" : "=l"(d) : "l"(a), "l"(b)); return d;
}
__device__ __forceinline__ u64 fma2(u64 a, u64 b, u64 c) {
    u64 d; asm("fma.rn.f32x2 %0,%1,%2,%3;" : "=l"(d) : "l"(a), "l"(b), "l"(c)); return d;
}
__device__ __forceinline__ u64 dup2(float v) {
    u64 d; asm("mov.b64 %0,{%1,%1};" : "=l"(d) : "f"(v)); return d;
}

// ---------------------------------------------------------------------------
// Fused GEMM over combined M=1536: rows [0,1024)=z_t@W1[:D],
// [1024,1536)=z_o@W1[D:]+b1.
// BM=128, BN=64, BK=32, 128 threads, micro 8m x 8n per thread.
// Smem bytes per thread per k: 32B (a, 8 floats) + 32B (b, 4 natural n-pairs)
// for 32 FFMA2 = 128 FLOP -> 0.5 B/FLOP (smem-BW parity with fma floor).
// A duplicated in registers (8 dup2 movs on alu pipe). Double-buffered,
// 1 sync per 32-k block. Grid (8 n-tiles, 12 m-tiles) = 96 CTAs.
// ---------------------------------------------------------------------------
__global__ __launch_bounds__(128) void gemm_kernel(
    const float* __restrict__ z_t, const float* __restrict__ z_o,
    const float* __restrict__ W1,  const float* __restrict__ b1)
{
    __shared__ float As[2][32][132];   // [buf][k][m]; 528B row (16B-mult)
    __shared__ float Bs[2][32][68];    // [buf][k][n]; 272B row (16B-mult)

    const int tid = threadIdx.x;
    const int mt  = blockIdx.y;             // 0..11
    const int n0  = blockIdx.x << 6;        // 0..448
    const bool isHo = (mt >= 8);
    const int m0 = (isHo ? (mt - 8) : mt) << 7;
    const float* A = isHo ? z_o : z_t;
    const float* B = isHo ? (W1 + (u64)DD * HH) : W1;
    float* C = isHo ? g_ho : g_ht;

    // A staging: thread = one m row (tid), 8 float4 along k (32 k).
    // B staging: brow = tid>>2 (k), bc = (tid&3)*16 floats (4 float4 in n).
    const int brow = tid >> 2;
    const int bc   = (tid & 3) << 4;

    // compute indices: 8n per thread at n = tx*8, 8m at m = ty*8
    const int tx = tid & 7;
    const int ty = tid >> 3;                // 0..15

    u64 acc[8][4];
    #pragma unroll
    for (int m = 0; m < 8; m++)
        #pragma unroll
        for (int j = 0; j < 4; j++) acc[m][j] = 0ull;

    const float* aptr = &A[(u64)(m0 + tid) * DD];
    const float* bptr = &B[(u64)brow * HH + n0 + bc];

    float4 va[8], vb[4];

    // ---- prologue: stage 0 ----
    #pragma unroll
    for (int q = 0; q < 8; q++)
        va[q] = *reinterpret_cast<const float4*>(aptr + (q << 2));
    #pragma unroll
    for (int q = 0; q < 4; q++)
        vb[q] = *reinterpret_cast<const float4*>(bptr + (q << 2));

    #pragma unroll
    for (int q = 0; q < 8; q++) {
        As[0][(q << 2) + 0][tid] = va[q].x;
        As[0][(q << 2) + 1][tid] = va[q].y;
        As[0][(q << 2) + 2][tid] = va[q].z;
        As[0][(q << 2) + 3][tid] = va[q].w;
    }
    #pragma unroll
    for (int q = 0; q < 4; q++)
        *reinterpret_cast<float4*>(&Bs[0][brow][bc + (q << 2)]) = vb[q];
    __syncthreads();

    #pragma unroll 1
    for (int kb = 0; kb < 8; kb++) {
        const int cur = kb & 1, nxt = cur ^ 1;

        if (kb < 7) {   // next stage's global loads, hidden under compute
            const float* ap = aptr + ((kb + 1) << 5);
            #pragma unroll
            for (int q = 0; q < 8; q++)
                va[q] = *reinterpret_cast<const float4*>(ap + (q << 2));
            const float* bp = bptr + (u64)((kb + 1) << 5) * HH;
            #pragma unroll
            for (int q = 0; q < 4; q++)
                vb[q] = *reinterpret_cast<const float4*>(bp + (u64)(q << 2));
        }

        #pragma unroll
        for (int k = 0; k < 32; k++) {
            float4 af0 = *reinterpret_cast<const float4*>(&As[cur][k][ty << 3]);
            float4 af1 = *reinterpret_cast<const float4*>(&As[cur][k][(ty << 3) + 4]);
            ulonglong2 b01 = *reinterpret_cast<const ulonglong2*>(&Bs[cur][k][tx << 3]);
            ulonglong2 b23 = *reinterpret_cast<const ulonglong2*>(&Bs[cur][k][(tx << 3) + 4]);
            u64 ad[8];
            ad[0] = dup2(af0.x); ad[1] = dup2(af0.y);
            ad[2] = dup2(af0.z); ad[3] = dup2(af0.w);
            ad[4] = dup2(af1.x); ad[5] = dup2(af1.y);
            ad[6] = dup2(af1.z); ad[7] = dup2(af1.w);
            #pragma unroll
            for (int m = 0; m < 8; m++) {
                acc[m][0] = fma2(ad[m], b01.x, acc[m][0]);
                acc[m][1] = fma2(ad[m], b01.y, acc[m][1]);
                acc[m][2] = fma2(ad[m], b23.x, acc[m][2]);
                acc[m][3] = fma2(ad[m], b23.y, acc[m][3]);
            }
        }

        if (kb < 7) {   // store into the other buffer, then sync
            #pragma unroll
            for (int q = 0; q < 8; q++) {
                As[nxt][(q << 2) + 0][tid] = va[q].x;
                As[nxt][(q << 2) + 1][tid] = va[q].y;
                As[nxt][(q << 2) + 2][tid] = va[q].z;
                As[nxt][(q << 2) + 3][tid] = va[q].w;
            }
            #pragma unroll
            for (int q = 0; q < 4; q++)
                *reinterpret_cast<float4*>(&Bs[nxt][brow][bc + (q << 2)]) = vb[q];
            __syncthreads();
        }
    }

    // epilogue: thread's n range is contiguous: n0 + tx*8 .. +7
    float4 bvA = make_float4(0.f, 0.f, 0.f, 0.f);
    float4 bvB = make_float4(0.f, 0.f, 0.f, 0.f);
    if (isHo) {
        bvA = *reinterpret_cast<const float4*>(&b1[n0 + (tx << 3)]);
        bvB = *reinterpret_cast<const float4*>(&b1[n0 + (tx << 3) + 4]);
    }

    #pragma unroll
    for (int m = 0; m < 8; m++) {
        float2 p0 = *reinterpret_cast<float2*>(&acc[m][0]);
        float2 p1 = *reinterpret_cast<float2*>(&acc[m][1]);
        float2 p2 = *reinterpret_cast<float2*>(&acc[m][2]);
        float2 p3 = *reinterpret_cast<float2*>(&acc[m][3]);
        float4 r0 = make_float4(p0.x + bvA.x, p0.y + bvA.y, p1.x + bvA.z, p1.y + bvA.w);
        float4 r1 = make_float4(p2.x + bvB.x, p2.y + bvB.y, p3.x + bvB.z, p3.y + bvB.w);
        int r = m0 + (ty << 3) + m;
        *reinterpret_cast<float4*>(&C[(u64)r * HH + n0 + (tx << 3)])     = r0;
        *reinterpret_cast<float4*>(&C[(u64)r * HH + n0 + (tx << 3) + 4]) = r1;
    }
}

// ---------------------------------------------------------------------------
// Per-row linear terms: ct[t] = 0.505*<ht[t],W2>, co[o] = 0.505*<ho[o],W2>+b2
// ---------------------------------------------------------------------------
__global__ __launch_bounds__(256) void reduce_kernel(
    const float* __restrict__ W2, const float* __restrict__ b2)
{
    int warp = (blockIdx.x * blockDim.x + threadIdx.x) >> 5;
    int lane = threadIdx.x & 31;
    const float* row;
    float* dst;
    float extra = 0.f;
    if (warp < TT) { row = g_ht + (u64)warp * HH; dst = g_ct + warp; }
    else { row = g_ho + (u64)(warp - TT) * HH; dst = g_co + (warp - TT); extra = b2[0]; }
    float s = 0.f;
    #pragma unroll
    for (int i = 0; i < 4; i++) {
        float4 v = *reinterpret_cast<const float4*>(&row[(lane + 32 * i) << 2]);
        float4 w = *reinterpret_cast<const float4*>(&W2[(lane + 32 * i) << 2]);
        s += v.x * w.x + v.y * w.y + v.z * w.z + v.w * w.w;
    }
    #pragma unroll
    for (int off = 16; off; off >>= 1) s += __shfl_xor_sync(0xffffffffu, s, off);
    if (lane == 0) *dst = 0.505f * s + extra;
}

// ---------------------------------------------------------------------------
// Pairwise kernel: out[t,o] = ct[t]+co[o] + sum_h |ht+ho| * (0.495*W2[h])
// 64x64 tile, 512 threads (4 warps/SMSP), micro 2t x 4o, packed f32x2 inner.
// ---------------------------------------------------------------------------
__global__ __launch_bounds__(512) void pair_kernel(
    const float* __restrict__ W2, float* __restrict__ out)
{
    __shared__ float4 sA[16][65];      // [hq][t]
    __shared__ float4 sB[16][65];      // [hq][o]
    __shared__ float4 sW[HH / 4];      // 0.495*W2 quads

    const int tid = threadIdx.x;
    const int tx = tid & 15;           // o lane (o = tx + 16j)
    const int ty = (tid >> 4) & 31;    // t lane (t = ty + 32i)
    const int t0 = blockIdx.y << 6;
    const int o0 = blockIdx.x << 6;

    if (tid < HH / 4) {
        float4 w = *reinterpret_cast<const float4*>(&W2[tid << 2]);
        w.x *= 0.495f; w.y *= 0.495f; w.z *= 0.495f; w.w *= 0.495f;
        sW[tid] = w;
    }

    u64 acc[2][4];
    #pragma unroll
    for (int i = 0; i < 2; i++)
        #pragma unroll
        for (int j = 0; j < 4; j++) acc[i][j] = 0ull;

    const int hs  = tid & 15;          // hq for staging
    const int ts2 = tid >> 4;          // 0..31
    const u64 SMASK = 0x7fffffff7fffffffULL;

    const float* pa0 = &g_ht[(u64)(t0 + ts2)      * HH + (hs << 2)];
    const float* pa1 = &g_ht[(u64)(t0 + ts2 + 32) * HH + (hs << 2)];
    const float* pb0 = &g_ho[(u64)(o0 + ts2)      * HH + (hs << 2)];
    const float* pb1 = &g_ho[(u64)(o0 + ts2 + 32) * HH + (hs << 2)];

    float4 va0 = *reinterpret_cast<const float4*>(pa0);
    float4 va1 = *reinterpret_cast<const float4*>(pa1);
    float4 vb0 = *reinterpret_cast<const float4*>(pb0);
    float4 vb1 = *reinterpret_cast<const float4*>(pb1);

    #pragma unroll 1
    for (int c = 0; c < 8; c++) {      // 8 chunks of 64 h
        __syncthreads();
        sA[hs][ts2] = va0; sA[hs][ts2 + 32] = va1;
        sB[hs][ts2] = vb0; sB[hs][ts2 + 32] = vb1;
        __syncthreads();

        if (c < 7) {                   // prefetch next chunk under compute
            int off = (c + 1) << 6;
            va0 = *reinterpret_cast<const float4*>(pa0 + off);
            va1 = *reinterpret_cast<const float4*>(pa1 + off);
            vb0 = *reinterpret_cast<const float4*>(pb0 + off);
            vb1 = *reinterpret_cast<const float4*>(pb1 + off);
        }

        #pragma unroll
        for (int hq = 0; hq < 16; hq++) {
            ulonglong2 w = *reinterpret_cast<const ulonglong2*>(&sW[(c << 4) + hq]);
            ulonglong2 a[2], b[4];
            #pragma unroll
            for (int i = 0; i < 2; i++)
                a[i] = *reinterpret_cast<const ulonglong2*>(&sA[hq][ty + (i << 5)]);
            #pragma unroll
            for (int j = 0; j < 4; j++)
                b[j] = *reinterpret_cast<const ulonglong2*>(&sB[hq][tx + (j << 4)]);
            #pragma unroll
            for (int i = 0; i < 2; i++)
                #pragma unroll
                for (int j = 0; j < 4; j++) {
                    u64 x = add2(a[i].x, b[j].x) & SMASK;
                    acc[i][j] = fma2(x, w.x, acc[i][j]);
                    u64 y = add2(a[i].y, b[j].y) & SMASK;
                    acc[i][j] = fma2(y, w.y, acc[i][j]);
                }
        }
    }

    float ctv[2], cov[4];
    #pragma unroll
    for (int i = 0; i < 2; i++) ctv[i] = g_ct[t0 + ty + (i << 5)];
    #pragma unroll
    for (int j = 0; j < 4; j++) cov[j] = g_co[o0 + tx + (j << 4)];
    #pragma unroll
    for (int i = 0; i < 2; i++)
        #pragma unroll
        for (int j = 0; j < 4; j++) {
            float2 p = *reinterpret_cast<float2*>(&acc[i][j]);
            out[(u64)(t0 + ty + (i << 5)) * OO + o0 + tx + (j << 4)]
                = ctv[i] + cov[j] + p.x + p.y;
        }
}

extern "C" void kernel_launch(void* const* d_in, const int* in_sizes, int n_in,
                              void* d_out, int out_size)
{
    const float* z_t = (const float*)d_in[0];   // [1024,256]
    const float* z_o = (const float*)d_in[1];   // [512,256]
    const float* W1  = (const float*)d_in[2];   // [512,512]
    const float* b1  = (const float*)d_in[3];   // [512]
    const float* W2  = (const float*)d_in[4];   // [512,1]
    const float* b2  = (const float*)d_in[5];   // [1]
    float* out = (float*)d_out;                 // [1024,512]

    gemm_kernel<<<dim3(8, 12), 128>>>(z_t, z_o, W1, b1);
    reduce_kernel<<<192, 256>>>(W2, b2);
    pair_kernel<<<dim3(OO / 64, TT / 64), 512>>>(W2, out);
}